// round 5
// baseline (speedup 1.0000x reference)
#include <cuda_runtime.h>

#define NTOT      40
#define NX        20
#define BATCHN    524288
#define TPB       320                 // 32 rows * 10 float4-chunks per row
#define ROWS_TILE 32
#define ITERS     4
#define ROWS_BLOCK (ROWS_TILE * ITERS)       // 128 rows per block
#define NBLOCKS   (BATCHN / ROWS_BLOCK)      // 4096

// Per-block double partials (deterministic, no atomics, no zero-init needed:
// every block writes its own slot every launch).
__device__ double g_part_dd[NBLOCKS];
__device__ double g_part_pi[NBLOCKS];

__global__ __launch_bounds__(TPB) void hybrid_loss_kernel(
    const float* __restrict__ pred,
    const float* __restrict__ targ,
    const float* __restrict__ ycur)
{
    __shared__ __align__(16) float sp[ROWS_TILE][44];   // 44-stride pad, 16B-aligned rows

    const int t = threadIdx.x;
    const int r = t / 10;           // row within tile (0..31)
    const int j = t - r * 10;       // float4 chunk within row (0..9)

    const float4* __restrict__ p4 = (const float4*)pred;
    const float4* __restrict__ y4 = (const float4*)ycur;
    const float2* __restrict__ t2 = (const float2*)targ;

    const int base_row = blockIdx.x * ROWS_BLOCK;

    float acc_dd = 0.0f;
    float acc_pi = 0.0f;

    // Prefetch iteration 0 (pred/y fully coalesced float4; targ float2 over needed cols)
    float4 pv = p4[base_row * 10 + t];
    float4 yv = y4[base_row * 10 + t];
    float2 tv = t2[(base_row + r) * 20 + j];

    // Stencil neighbor indices within the 40-wide row (compile-ish cheap selects)
    const int i0  = 4 * j;
    const int im2 = (j == 0) ? 38 : i0 - 2;
    const int im1 = (j == 0) ? 39 : i0 - 1;
    const int ip1 = (j == 9) ? 0  : i0 + 4;

    #pragma unroll
    for (int it = 0; it < ITERS; ++it) {
        float4 pc = pv;
        float4 yc = yv;
        float2 tc = tv;

        // Prefetch next tile before consuming smem — LDG latency overlaps barrier+compute
        if (it + 1 < ITERS) {
            int nb = base_row + (it + 1) * ROWS_TILE;
            pv = p4[nb * 10 + t];
            yv = y4[nb * 10 + t];
            tv = t2[(nb + r) * 20 + j];
        }

        // Stage pred tile in smem (float4 store: row stride 176B, 16B aligned)
        *reinterpret_cast<float4*>(&sp[r][i0]) = pc;
        __syncthreads();

        // ---- data-driven term: elements 2j, 2j+1 of row r (covers cols 0..19) ----
        {
            float d0 = sp[r][2 * j]     - tc.x;
            float d1 = sp[r][2 * j + 1] - tc.y;
            acc_dd += d0 * d0 + d1 * d1;
        }

        // ---- physics term: elements 4j..4j+3, Lorenz-96 RHS with periodic wrap ----
        {
            float pm2 = sp[r][im2];
            float pm1 = sp[r][im1];
            float pp1 = sp[r][ip1];
            float p0 = pc.x, p1 = pc.y, p2 = pc.z, p3 = pc.w;

            float f0 = (p1  - pm2) * pm1 - p0 + 8.0f;
            float f1 = (p2  - pm1) * p0  - p1 + 8.0f;
            float f2 = (p3  - p0 ) * p1  - p2 + 8.0f;
            float f3 = (pp1 - p1 ) * p2  - p3 + 8.0f;

            float d0 = (p0 - yc.x) * 100.0f - f0;
            float d1 = (p1 - yc.y) * 100.0f - f1;
            float d2 = (p2 - yc.z) * 100.0f - f2;
            float d3 = (p3 - yc.w) * 100.0f - f3;

            acc_pi += d0 * d0 + d1 * d1 + d2 * d2 + d3 * d3;
        }
        __syncthreads();   // protect smem before next iteration's store
    }

    // ---- block reduction: warp shuffle (float) -> smem (double) -> one write ----
    #pragma unroll
    for (int o = 16; o; o >>= 1) {
        acc_dd += __shfl_xor_sync(0xFFFFFFFFu, acc_dd, o);
        acc_pi += __shfl_xor_sync(0xFFFFFFFFu, acc_pi, o);
    }
    __shared__ double wdd[TPB / 32], wpi[TPB / 32];
    int lane = t & 31, w = t >> 5;
    if (lane == 0) { wdd[w] = (double)acc_dd; wpi[w] = (double)acc_pi; }
    __syncthreads();
    if (t == 0) {
        double a = 0.0, b = 0.0;
        #pragma unroll
        for (int i = 0; i < TPB / 32; ++i) { a += wdd[i]; b += wpi[i]; }
        g_part_dd[blockIdx.x] = a;
        g_part_pi[blockIdx.x] = b;
    }
}

__global__ void finalize_kernel(float* __restrict__ out)
{
    const int t = threadIdx.x;
    double a = 0.0, b = 0.0;
    for (int i = t; i < NBLOCKS; i += blockDim.x) {
        a += g_part_dd[i];
        b += g_part_pi[i];
    }
    #pragma unroll
    for (int o = 16; o; o >>= 1) {
        a += __shfl_xor_sync(0xFFFFFFFFu, a, o);
        b += __shfl_xor_sync(0xFFFFFFFFu, b, o);
    }
    __shared__ double sa[16], sb[16];
    int lane = t & 31, w = t >> 5;
    if (lane == 0) { sa[w] = a; sb[w] = b; }
    __syncthreads();
    if (t == 0) {
        double A = 0.0, B = 0.0;
        for (int i = 0; i < (int)blockDim.x / 32; ++i) { A += sa[i]; B += sb[i]; }
        double l_dd = A / ((double)BATCHN * (double)NX);
        double l_pi = B / ((double)BATCHN * (double)NTOT);
        out[0] = (float)(l_dd + 0.1 * l_pi);   // total_loss
        out[1] = (float)l_dd;
        out[2] = (float)l_pi;
    }
}

extern "C" void kernel_launch(void* const* d_in, const int* in_sizes, int n_in,
                              void* d_out, int out_size)
{
    const float* pred = (const float*)d_in[0];   // predictions [524288, 40]
    const float* targ = (const float*)d_in[1];   // targets     [524288, 40]
    const float* ycur = (const float*)d_in[2];   // y_current   [524288, 40]
    float* out = (float*)d_out;                  // [total, l_dd, l_pi]

    hybrid_loss_kernel<<<NBLOCKS, TPB>>>(pred, targ, ycur);
    finalize_kernel<<<1, 512>>>(out);
}

// round 6
// speedup vs baseline: 1.0220x; 1.0220x over previous
#include <cuda_runtime.h>

#define NTOT      40
#define NX        20
#define BATCHN    524288
#define TPB       320                 // 32 rows * 10 float4-chunks per row
#define ROWS_TILE 32
#define ITERS     8
#define ROWS_BLOCK (ROWS_TILE * ITERS)       // 256 rows per block
#define NBLOCKS   (BATCHN / ROWS_BLOCK)      // 2048

// Per-block double partials (each block writes its own slot every launch).
__device__ double g_part_dd[NBLOCKS];
__device__ double g_part_pi[NBLOCKS];
__device__ unsigned int g_ticket = 0;   // reset to 0 by the last block each launch

__global__ __launch_bounds__(TPB) void hybrid_loss_kernel(
    const float* __restrict__ pred,
    const float* __restrict__ targ,
    const float* __restrict__ ycur,
    float* __restrict__ out)
{
    // Double-buffered pred staging: one barrier per tile instead of two.
    __shared__ __align__(16) float sp[2][ROWS_TILE][44];

    const int t = threadIdx.x;
    const int r = t / 10;           // row within tile (0..31)
    const int j = t - r * 10;       // float4 chunk within row (0..9)

    const float4* __restrict__ p4 = (const float4*)pred;
    const float4* __restrict__ y4 = (const float4*)ycur;
    const float4* __restrict__ t4 = (const float4*)targ;

    const int base_row = blockIdx.x * ROWS_BLOCK;

    float acc_dd = 0.0f;
    float acc_pi = 0.0f;

    // Prefetch iteration 0. pred/ycur fully coalesced float4.
    // targets: only threads j<5 load (cols 4j..4j+3 cover the observed 0..19).
    float4 pv = p4[base_row * 10 + t];
    float4 yv = y4[base_row * 10 + t];
    float4 tv = (j < 5) ? t4[(base_row + r) * 10 + j] : make_float4(0.f, 0.f, 0.f, 0.f);

    // Stencil neighbor indices within the 40-wide row (periodic wrap).
    const int i0  = 4 * j;
    const int im2 = (j == 0) ? 38 : i0 - 2;
    const int im1 = (j == 0) ? 39 : i0 - 1;
    const int ip1 = (j == 9) ? 0  : i0 + 4;

    #pragma unroll
    for (int it = 0; it < ITERS; ++it) {
        const int buf = it & 1;
        float4 pc = pv;
        float4 yc = yv;
        float4 tc = tv;

        // Prefetch next tile before the barrier — LDG latency overlaps barrier+compute.
        if (it + 1 < ITERS) {
            int nb = base_row + (it + 1) * ROWS_TILE;
            pv = p4[nb * 10 + t];
            yv = y4[nb * 10 + t];
            if (j < 5) tv = t4[(nb + r) * 10 + j];
        }

        // Stage pred tile (float4 store, 176B row stride, 16B aligned).
        *reinterpret_cast<float4*>(&sp[buf][r][i0]) = pc;
        __syncthreads();

        // ---- data-driven term: j<5 owns pred cols 4j..4j+3 in registers ----
        if (j < 5) {
            float d0 = pc.x - tc.x;
            float d1 = pc.y - tc.y;
            float d2 = pc.z - tc.z;
            float d3 = pc.w - tc.w;
            acc_dd += d0 * d0 + d1 * d1 + d2 * d2 + d3 * d3;
        }

        // ---- physics term: Lorenz-96 RHS, 3 smem neighbor reads only ----
        {
            float pm2 = sp[buf][r][im2];
            float pm1 = sp[buf][r][im1];
            float pp1 = sp[buf][r][ip1];
            float p0 = pc.x, p1 = pc.y, p2 = pc.z, p3 = pc.w;

            float f0 = (p1  - pm2) * pm1 - p0 + 8.0f;
            float f1 = (p2  - pm1) * p0  - p1 + 8.0f;
            float f2 = (p3  - p0 ) * p1  - p2 + 8.0f;
            float f3 = (pp1 - p1 ) * p2  - p3 + 8.0f;

            float d0 = (p0 - yc.x) * 100.0f - f0;
            float d1 = (p1 - yc.y) * 100.0f - f1;
            float d2 = (p2 - yc.z) * 100.0f - f2;
            float d3 = (p3 - yc.w) * 100.0f - f3;

            acc_pi += d0 * d0 + d1 * d1 + d2 * d2 + d3 * d3;
        }
        // No trailing barrier: next iteration writes the other buffer; its
        // leading __syncthreads orders this iteration's reads before the
        // write that next reuses this buffer (two barriers in between).
    }

    // ---- block reduction: warp shuffle (float) -> smem (double) ----
    #pragma unroll
    for (int o = 16; o; o >>= 1) {
        acc_dd += __shfl_xor_sync(0xFFFFFFFFu, acc_dd, o);
        acc_pi += __shfl_xor_sync(0xFFFFFFFFu, acc_pi, o);
    }
    __shared__ double wdd[TPB / 32], wpi[TPB / 32];
    __shared__ int s_last;
    int lane = t & 31, w = t >> 5;
    if (lane == 0) { wdd[w] = (double)acc_dd; wpi[w] = (double)acc_pi; }
    __syncthreads();
    if (t == 0) {
        double a = 0.0, b = 0.0;
        #pragma unroll
        for (int i = 0; i < TPB / 32; ++i) { a += wdd[i]; b += wpi[i]; }
        g_part_dd[blockIdx.x] = a;
        g_part_pi[blockIdx.x] = b;
        __threadfence();
        unsigned int v = atomicAdd(&g_ticket, 1u);
        s_last = (v == (unsigned int)(gridDim.x - 1));
    }
    __syncthreads();

    // ---- last block performs the final reduction (fixed order: deterministic) ----
    if (s_last) {
        double a = 0.0, b = 0.0;
        for (int i = t; i < NBLOCKS; i += TPB) {
            a += g_part_dd[i];
            b += g_part_pi[i];
        }
        #pragma unroll
        for (int o = 16; o; o >>= 1) {
            a += __shfl_xor_sync(0xFFFFFFFFu, a, o);
            b += __shfl_xor_sync(0xFFFFFFFFu, b, o);
        }
        if (lane == 0) { wdd[w] = a; wpi[w] = b; }
        __syncthreads();
        if (t == 0) {
            double A = 0.0, B = 0.0;
            #pragma unroll
            for (int i = 0; i < TPB / 32; ++i) { A += wdd[i]; B += wpi[i]; }
            double l_dd = A / ((double)BATCHN * (double)NX);
            double l_pi = B / ((double)BATCHN * (double)NTOT);
            out[0] = (float)(l_dd + 0.1 * l_pi);   // total_loss
            out[1] = (float)l_dd;
            out[2] = (float)l_pi;
            g_ticket = 0;   // re-arm for the next graph replay
        }
    }
}

extern "C" void kernel_launch(void* const* d_in, const int* in_sizes, int n_in,
                              void* d_out, int out_size)
{
    const float* pred = (const float*)d_in[0];   // predictions [524288, 40]
    const float* targ = (const float*)d_in[1];   // targets     [524288, 40]
    const float* ycur = (const float*)d_in[2];   // y_current   [524288, 40]
    float* out = (float*)d_out;                  // [total, l_dd, l_pi]

    hybrid_loss_kernel<<<NBLOCKS, TPB>>>(pred, targ, ycur, out);
}